// round 6
// baseline (speedup 1.0000x reference)
#include <cuda_runtime.h>
#include <math.h>
#include <stdint.h>

#define VOCAB    32000
#define V4       8000                // float4 per row
#define NROWS    4092                // 4 * 1023
#define SEQ      1024
#define TPB      1024
#define MAXCTA   256

#define CHUNK_B   32000              // bytes per chunk (row = 4 chunks)
#define CHUNK_Q   2000               // quads per chunk
#define NBUF      3
#define TH_BYTES  (VOCAB * 4)        // 128000
#define DYN_SMEM  (TH_BYTES + NBUF * CHUNK_B)   // 224000

__device__ double   g_part[MAXCTA];
__device__ unsigned g_cnt = 0;

typedef unsigned long long u64;

// ---------- packed f32x2 helpers ----------
__device__ __forceinline__ u64 pack2(float lo, float hi) {
    u64 r; asm("mov.b64 %0, {%1,%2};" : "=l"(r) : "f"(lo), "f"(hi)); return r;
}
__device__ __forceinline__ void unpack2(u64 v, float& lo, float& hi) {
    asm("mov.b64 {%0,%1}, %2;" : "=f"(lo), "=f"(hi) : "l"(v));
}
__device__ __forceinline__ u64 fma2(u64 a, u64 b, u64 c) {
    u64 d; asm("fma.rn.f32x2 %0, %1, %2, %3;" : "=l"(d) : "l"(a), "l"(b), "l"(c)); return d;
}
__device__ __forceinline__ u64 mul2(u64 a, u64 b) {
    u64 d; asm("mul.rn.f32x2 %0, %1, %2;" : "=l"(d) : "l"(a), "l"(b)); return d;
}
__device__ __forceinline__ u64 add2(u64 a, u64 b) {
    u64 d; asm("add.rn.f32x2 %0, %1, %2;" : "=l"(d) : "l"(a), "l"(b)); return d;
}

#define PC(x) ((u64)(x) | ((u64)(x) << 32))
#define K_CM1  PC(0xBF800000u)  // -1.0
#define K_C1   PC(0x3F800000u)  //  1.0
#define K_C2   PC(0xBF000000u)  // -0.5
#define K_C3   PC(0x3EAAAAABu)  //  1/3
#define K_C4   PC(0xBE800000u)  // -1/4
#define K_C5   PC(0x3E4CCCCDu)  //  1/5
#define K_LN2  PC(0x3F317218u)  //  ln 2
#define K_MAG  PC(0xCB400000u)  // -12582912.0f

// ---------- mbarrier / bulk-async ----------
__device__ __forceinline__ uint32_t smem_u32(const void* p) {
    uint32_t a;
    asm("{ .reg .u64 t; cvta.to.shared.u64 t, %1; cvt.u32.u64 %0, t; }" : "=r"(a) : "l"(p));
    return a;
}
__device__ __forceinline__ void mbar_init(uint32_t mbar, uint32_t cnt) {
    asm volatile("mbarrier.init.shared.b64 [%0], %1;" :: "r"(mbar), "r"(cnt) : "memory");
}
__device__ __forceinline__ void mbar_expect_tx(uint32_t mbar, uint32_t bytes) {
    asm volatile("mbarrier.arrive.expect_tx.shared.b64 _, [%0], %1;" :: "r"(mbar), "r"(bytes) : "memory");
}
__device__ __forceinline__ void mbar_wait(uint32_t mbar, uint32_t parity) {
    uint32_t done;
    asm volatile(
        "{\n\t.reg .pred p;\n\t"
        "mbarrier.try_wait.parity.acquire.cta.shared::cta.b64 p, [%1], %2;\n\t"
        "selp.b32 %0, 1, 0, p;\n\t}"
        : "=r"(done) : "r"(mbar), "r"(parity) : "memory");
    if (!done) {
        asm volatile(
            "{\n\t.reg .pred P1;\n\t"
            "WL_%=:\n\t"
            "mbarrier.try_wait.parity.acquire.cta.shared::cta.b64 P1, [%0], %1, 0x989680;\n\t"
            "@P1 bra.uni WD_%=;\n\t"
            "bra.uni WL_%=;\n\t"
            "WD_%=:\n\t}"
            :: "r"(mbar), "r"(parity) : "memory");
    }
}
__device__ __forceinline__ void bulk_ld(uint32_t dst, const void* src,
                                        uint32_t bytes, uint32_t mbar) {
    asm volatile(
        "cp.async.bulk.shared::cluster.global.mbarrier::complete_tx::bytes [%0], [%1], %2, [%3];"
        :: "r"(dst), "l"(src), "r"(bytes), "r"(mbar) : "memory");
}

// scalar fast log (prologue only): degree-5, |abs err| <= 2e-4
__device__ __forceinline__ float lnfast(float x) {
    int i = __float_as_int(x);
    int k = (i - 0x3F2AAAAB) & 0xFF800000;
    float f = __int_as_float(i - k) - 1.0f;
    float P = 0.2f;
    P = fmaf(P, f, -0.25f);
    P = fmaf(P, f,  0.33333334f);
    P = fmaf(P, f, -0.5f);
    P = fmaf(P, f,  1.0f);
    return fmaf(f, P, (float)k * 8.2629582e-8f);
}

__device__ __forceinline__ float warp_sum(float v) {
    #pragma unroll
    for (int o = 16; o; o >>= 1) v += __shfl_xor_sync(0xFFFFFFFFu, v, o);
    return v;
}
__device__ __forceinline__ double warp_sum_d(double v) {
    #pragma unroll
    for (int o = 16; o; o >>= 1) v += __shfl_xor_sync(0xFFFFFFFFu, v, o);
    return v;
}

// packed range reduction, no I2F
__device__ __forceinline__ void lnprep2(int i0, int i1, u64& fm, u64& fe) {
    int d0 = i0 - 0x3F2AAAAB, d1 = i1 - 0x3F2AAAAB;
    int k0 = d0 & 0xFF800000, k1 = d1 & 0xFF800000;
    float m0 = __int_as_float(i0 - k0);
    float m1 = __int_as_float(i1 - k1);
    int t0 = (d0 >> 23) + 0x4B400000;
    int t1 = (d1 >> 23) + 0x4B400000;
    fm = add2(pack2(m0, m1), K_CM1);
    fe = add2(pack2(__int_as_float(t0), __int_as_float(t1)), K_MAG);
}

__device__ __forceinline__ void proc_quad(int4 vq, float4 wt, u64& accA, u64& accB) {
    u64 fmA, feA, fmB, feB;
    lnprep2(vq.x, vq.y, fmA, feA);
    lnprep2(vq.z, vq.w, fmB, feB);
    u64 QA = fma2(K_C5, fmA, K_C4);
    u64 QB = fma2(K_C5, fmB, K_C4);
    QA = fma2(QA, fmA, K_C3);  QB = fma2(QB, fmB, K_C3);
    QA = fma2(QA, fmA, K_C2);  QB = fma2(QB, fmB, K_C2);
    QA = fma2(QA, fmA, K_C1);  QB = fma2(QB, fmB, K_C1);
    u64 LA = fma2(fmA, QA, mul2(feA, K_LN2));
    u64 LB = fma2(fmB, QB, mul2(feB, K_LN2));
    accA = fma2(pack2(wt.x, wt.y), LA, accA);
    accB = fma2(pack2(wt.z, wt.w), LB, accB);
}

// row index (0..4091) -> float offset of row start ( (row + row/1023) * 32000 )
__device__ __forceinline__ size_t row_off(int row) {
    return (size_t)(row + row / 1023) * VOCAB;
}

__global__ void __launch_bounds__(TPB, 1)
main_kernel(const float* __restrict__ p,
            const int*   __restrict__ dec,
            const float* __restrict__ th,
            float* __restrict__ out) {
    extern __shared__ float smem_dyn[];
    float*  sth  = smem_dyn;                           // 128000 B
    char*   bufs = (char*)(smem_dyn) + TH_BYTES;       // 3 x 32000 B
    __shared__ float  redf[TPB / 32];
    __shared__ double redd[TPB / 32];
    __shared__ float  s_b[2];
    __shared__ int    s_last;
    __shared__ alignas(8) unsigned long long mbar_store[NBUF];

    const int tid = threadIdx.x;
    const uint32_t mb0 = smem_u32(&mbar_store[0]);

    // ---- load th into smem ----
    float4* sth4 = reinterpret_cast<float4*>(sth);
    const float4* th4 = reinterpret_cast<const float4*>(th);
    for (int i = tid; i < V4; i += TPB) sth4[i] = th4[i];

    if (tid == 0) {
        #pragma unroll
        for (int i = 0; i < NBUF; i++) mbar_init(mb0 + 8u * i, 1);
    }
    __syncthreads();

    // ---- kick off first NBUF chunk loads (producer cursor: prow, pc) ----
    int prow = blockIdx.x, pc = 0;
    if (tid == 0) {
        #pragma unroll
        for (int i = 0; i < NBUF; i++) {
            if (prow < NROWS) {
                uint32_t mb = mb0 + 8u * i;
                mbar_expect_tx(mb, CHUNK_B);
                bulk_ld(smem_u32(bufs + i * CHUNK_B),
                        p + row_off(prow) + (size_t)pc * (CHUNK_Q * 4),
                        CHUNK_B, mb);
            }
            if (++pc == 4) { pc = 0; prow += gridDim.x; }
        }
    } else {
        #pragma unroll
        for (int i = 0; i < NBUF; i++)
            if (++pc == 4) { pc = 0; prow += gridDim.x; }
    }

    // ---- prologue: usum ----
    {
        float s = 0.f;
        for (int i = tid; i < VOCAB; i += TPB) s += sth[i];
        s = warp_sum(s);
        if ((tid & 31) == 0) redf[tid >> 5] = s;
        __syncthreads();
        if (tid == 0) {
            float t = 0.f;
            #pragma unroll
            for (int w = 0; w < TPB / 32; w++) t += redf[w];
            s_b[0] = t;
        }
        __syncthreads();
    }
    const float usum  = s_b[0];
    const float inv01 = 0.1f / usum;

    // ---- prologue: C1 ----
    {
        float c = 0.f;
        for (int i = tid; i < VOCAB; i += TPB) {
            float x = sth[i] * inv01;
            c += x * lnfast(x);
        }
        c = warp_sum(c);
        if ((tid & 31) == 0) redf[tid >> 5] = c;
        __syncthreads();
        if (tid == 0) {
            float t = 0.f;
            #pragma unroll
            for (int w = 0; w < TPB / 32; w++) t += redf[w];
            s_b[1] = t;
        }
        __syncthreads();
    }
    const float C1 = s_b[1];

    double accD = 0.0;

    // ---- label-dependent O(1)-per-row terms ----
    {
        const int gid = blockIdx.x * TPB + tid;
        if (gid < NROWS) {
            const int b = gid / 1023;
            const int t = gid - b * 1023;
            const int l = __ldg(&dec[b * SEQ + t + 1]);
            if (l != 0) {
                float pl = __ldg(p + (size_t)(b * SEQ + t) * VOCAB + l);
                float x  = sth[l] * inv01;
                accD += (double)(C1
                                 - x * logf(x)
                                 + (x + 0.9f) * logf(x + 0.9f)
                                 - 0.9f * logf(pl));
            }
        }
    }

    // ---- bulk: smem-staged chunk pipeline ----
    float thrAcc = 0.f;
    int crow = blockIdx.x, cc = 0;      // consumer cursor
    int cb = 0, cpar = 0;               // consumer buffer + parity
    u64 accA = 0, accB = 0;

    while (crow < NROWS) {
        const uint32_t mb = mb0 + 8u * cb;
        mbar_wait(mb, cpar);

        const int4*   sb = reinterpret_cast<const int4*>(bufs + cb * CHUNK_B);
        const float4* wq = sth4 + cc * CHUNK_Q;

        int4 v0 = sb[tid];
        float4 w0 = wq[tid];
        int4 v1; float4 w1;
        const bool two = (tid < CHUNK_Q - TPB);   // 976
        if (two) { v1 = sb[tid + TPB]; w1 = wq[tid + TPB]; }
        proc_quad(v0, w0, accA, accB);
        if (two) proc_quad(v1, w1, accA, accB);

        __syncthreads();   // all reads of buffer cb complete

        // producer: refill this buffer with the chunk NBUF ahead
        if (prow < NROWS) {
            if (tid == 0) {
                mbar_expect_tx(mb, CHUNK_B);
                bulk_ld(smem_u32(bufs + cb * CHUNK_B),
                        p + row_off(prow) + (size_t)pc * (CHUNK_Q * 4),
                        CHUNK_B, mb);
            }
            if (++pc == 4) { pc = 0; prow += gridDim.x; }
        }

        // row boundary: fold masked row sum
        if (cc == 3) {
            const int b   = crow / 1023;
            const int lbl = __ldg(&dec[b * SEQ + (crow - b * 1023) + 1]);
            float a0, a1, b0, b1;
            unpack2(accA, a0, a1);
            unpack2(accB, b0, b1);
            if (lbl != 0) thrAcc += (a0 + b0) + (a1 + b1);
            accA = 0; accB = 0;
            cc = 0; crow += gridDim.x;
        } else {
            ++cc;
        }
        if (++cb == NBUF) { cb = 0; cpar ^= 1; }
    }

    accD += (double)thrAcc * (-0.1 / (double)usum);

    // ---- per-CTA reduction ----
    accD = warp_sum_d(accD);
    if ((tid & 31) == 0) redd[tid >> 5] = accD;
    __syncthreads();
    if (tid == 0) {
        double t = 0.0;
        #pragma unroll
        for (int w = 0; w < TPB / 32; w++) t += redd[w];
        g_part[blockIdx.x] = t;
        __threadfence();
        unsigned old = atomicAdd(&g_cnt, 1u);
        s_last = (old == gridDim.x - 1) ? 1 : 0;
    }
    __syncthreads();

    // ---- last CTA finalizes ----
    if (s_last) {
        double v = (tid < (int)gridDim.x) ? g_part[tid] : 0.0;
        v = warp_sum_d(v);
        if ((tid & 31) == 0) redd[tid >> 5] = v;
        __syncthreads();
        if (tid == 0) {
            double t = 0.0;
            #pragma unroll
            for (int w = 0; w < TPB / 32; w++) t += redd[w];
            out[0] = (float)(t / (double)NROWS);
            g_cnt = 0;                 // reset for next graph replay
        }
    }
}

extern "C" void kernel_launch(void* const* d_in, const int* in_sizes, int n_in,
                              void* d_out, int out_size) {
    const int*   dec = nullptr;
    const float* p   = nullptr;
    const float* th  = nullptr;
    for (int i = 0; i < n_in; ++i) {
        if (in_sizes[i] == 4 * SEQ)    dec = (const int*)d_in[i];
        else if (in_sizes[i] == VOCAB) th  = (const float*)d_in[i];
        else                           p   = (const float*)d_in[i];
    }

    cudaFuncSetAttribute(main_kernel,
                         cudaFuncAttributeMaxDynamicSharedMemorySize,
                         DYN_SMEM);

    int sms = 0;
    cudaDeviceGetAttribute(&sms, cudaDevAttrMultiProcessorCount, 0);
    if (sms <= 0) sms = 148;
    if (sms > MAXCTA) sms = MAXCTA;

    main_kernel<<<sms, TPB, DYN_SMEM>>>(p, dec, th, (float*)d_out);
}

// round 7
// speedup vs baseline: 1.1247x; 1.1247x over previous
#include <cuda_runtime.h>
#include <math.h>

#define VOCAB   32000
#define V4      8000                 // float4 per row
#define NROWS   4092                 // 4 * 1023
#define SEQ     1024
#define TPB     1024
#define TAILQ   (V4 - 7 * TPB)       // 832 tail quads (= 26 full warps)
#define MAXCTA  256

__device__ double   g_part[MAXCTA];
__device__ unsigned g_cnt = 0;

typedef unsigned long long u64;

// ---------- packed f32x2 helpers ----------
__device__ __forceinline__ u64 pack2(float lo, float hi) {
    u64 r; asm("mov.b64 %0, {%1,%2};" : "=l"(r) : "f"(lo), "f"(hi)); return r;
}
__device__ __forceinline__ void unpack2(u64 v, float& lo, float& hi) {
    asm("mov.b64 {%0,%1}, %2;" : "=f"(lo), "=f"(hi) : "l"(v));
}
__device__ __forceinline__ u64 fma2(u64 a, u64 b, u64 c) {
    u64 d; asm("fma.rn.f32x2 %0, %1, %2, %3;" : "=l"(d) : "l"(a), "l"(b), "l"(c)); return d;
}
__device__ __forceinline__ u64 mul2(u64 a, u64 b) {
    u64 d; asm("mul.rn.f32x2 %0, %1, %2;" : "=l"(d) : "l"(a), "l"(b)); return d;
}
__device__ __forceinline__ u64 add2(u64 a, u64 b) {
    u64 d; asm("add.rn.f32x2 %0, %1, %2;" : "=l"(d) : "l"(a), "l"(b)); return d;
}

#define PC(x) ((u64)(x) | ((u64)(x) << 32))
#define K_CM1  PC(0xBF800000u)  // -1.0
#define K_C1   PC(0x3F800000u)  //  1.0
#define K_C2   PC(0xBF000000u)  // -0.5
#define K_C3   PC(0x3EAAAAABu)  //  1/3
#define K_C4   PC(0xBE800000u)  // -1/4
#define K_C5   PC(0x3E4CCCCDu)  //  1/5
#define K_LN2  PC(0x3F317218u)  //  ln 2
#define K_MAG  PC(0xCB400000u)  // -12582912.0f

// scalar fast log (prologue only): degree-5, |abs err| <= 2e-4
__device__ __forceinline__ float lnfast(float x) {
    int i = __float_as_int(x);
    int k = (i - 0x3F2AAAAB) & 0xFF800000;
    float f = __int_as_float(i - k) - 1.0f;
    float P = 0.2f;
    P = fmaf(P, f, -0.25f);
    P = fmaf(P, f,  0.33333334f);
    P = fmaf(P, f, -0.5f);
    P = fmaf(P, f,  1.0f);
    return fmaf(f, P, (float)k * 8.2629582e-8f);
}

__device__ __forceinline__ float warp_sum(float v) {
    #pragma unroll
    for (int o = 16; o; o >>= 1) v += __shfl_xor_sync(0xFFFFFFFFu, v, o);
    return v;
}
__device__ __forceinline__ double warp_sum_d(double v) {
    #pragma unroll
    for (int o = 16; o; o >>= 1) v += __shfl_xor_sync(0xFFFFFFFFu, v, o);
    return v;
}

// packed range reduction, no I2F (exponent->float via magic-number subtract, exact)
__device__ __forceinline__ void lnprep2(int i0, int i1, u64& fm, u64& fe) {
    int d0 = i0 - 0x3F2AAAAB, d1 = i1 - 0x3F2AAAAB;
    int k0 = d0 & 0xFF800000, k1 = d1 & 0xFF800000;
    float m0 = __int_as_float(i0 - k0);
    float m1 = __int_as_float(i1 - k1);
    int t0 = (d0 >> 23) + 0x4B400000;
    int t1 = (d1 >> 23) + 0x4B400000;
    fm = add2(pack2(m0, m1), K_CM1);
    fe = add2(pack2(__int_as_float(t0), __int_as_float(t1)), K_MAG);
}

// one quad: acc{A,B} += wt * ln(vq)
__device__ __forceinline__ void proc_quad(int4 vq, float4 wt, u64& accA, u64& accB) {
    u64 fmA, feA, fmB, feB;
    lnprep2(vq.x, vq.y, fmA, feA);
    lnprep2(vq.z, vq.w, fmB, feB);
    u64 QA = fma2(K_C5, fmA, K_C4);
    u64 QB = fma2(K_C5, fmB, K_C4);
    QA = fma2(QA, fmA, K_C3);  QB = fma2(QB, fmB, K_C3);
    QA = fma2(QA, fmA, K_C2);  QB = fma2(QB, fmB, K_C2);
    QA = fma2(QA, fmA, K_C1);  QB = fma2(QB, fmB, K_C1);
    u64 LA = fma2(fmA, QA, mul2(feA, K_LN2));
    u64 LB = fma2(fmB, QB, mul2(feB, K_LN2));
    accA = fma2(pack2(wt.x, wt.y), LA, accA);
    accB = fma2(pack2(wt.z, wt.w), LB, accB);
}

// row -> base quad pointer ( b*1024 + t = row + row/1023 )
__device__ __forceinline__ const int4* row_ptr(const float* p, int row) {
    int off = row + row / 1023;
    return reinterpret_cast<const int4*>(p + (size_t)off * VOCAB);
}

__device__ __forceinline__ void pf_l2(const void* ptr) {
    asm volatile("prefetch.global.L2 [%0];" :: "l"(ptr));
}

__global__ void __launch_bounds__(TPB, 1)
main_kernel(const float* __restrict__ p,
            const int*   __restrict__ dec,
            const float* __restrict__ th,
            float* __restrict__ out) {
    extern __shared__ float sth[];               // 32000 floats = 128 KB
    __shared__ float  redf[TPB / 32];
    __shared__ double redd[TPB / 32];
    __shared__ float  s_b[2];
    __shared__ int    s_last;

    const int tid = threadIdx.x;
    float4* sth4 = reinterpret_cast<float4*>(sth);
    const float4* th4 = reinterpret_cast<const float4*>(th);
    for (int i = tid; i < V4; i += TPB) sth4[i] = th4[i];
    __syncthreads();

    // ---- prologue: usum ----
    {
        float s = 0.f;
        for (int i = tid; i < VOCAB; i += TPB) s += sth[i];
        s = warp_sum(s);
        if ((tid & 31) == 0) redf[tid >> 5] = s;
        __syncthreads();
        if (tid == 0) {
            float t = 0.f;
            #pragma unroll
            for (int w = 0; w < TPB / 32; w++) t += redf[w];
            s_b[0] = t;
        }
        __syncthreads();
    }
    const float usum  = s_b[0];
    const float inv01 = 0.1f / usum;

    // ---- prologue: C1 ----
    {
        float c = 0.f;
        for (int i = tid; i < VOCAB; i += TPB) {
            float x = sth[i] * inv01;
            c += x * lnfast(x);
        }
        c = warp_sum(c);
        if ((tid & 31) == 0) redf[tid >> 5] = c;
        __syncthreads();
        if (tid == 0) {
            float t = 0.f;
            #pragma unroll
            for (int w = 0; w < TPB / 32; w++) t += redf[w];
            s_b[1] = t;
        }
        __syncthreads();
    }
    const float C1 = s_b[1];

    double accD = 0.0;

    // ---- label-dependent O(1)-per-row terms ----
    {
        const int gid = blockIdx.x * TPB + tid;
        if (gid < NROWS) {
            const int b = gid / 1023;
            const int t = gid - b * 1023;
            const int l = __ldg(&dec[b * SEQ + t + 1]);
            if (l != 0) {
                float pl = __ldg(p + (size_t)(b * SEQ + t) * VOCAB + l);
                float x  = sth[l] * inv01;
                accD += (double)(C1
                                 - x * logf(x)
                                 + (x + 0.9f) * logf(x + 0.9f)
                                 - 0.9f * logf(pl));
            }
        }
    }

    // ---- bulk: row loop with next-row L2 prefetch ----
    const bool hasTail = (tid < TAILQ);
    float thrAcc = 0.f;

    for (int row = blockIdx.x; row < NROWS; row += gridDim.x) {
        const int b   = row / 1023;
        const int lbl = __ldg(&dec[b * SEQ + (row - b * 1023) + 1]);
        const int4* cp = row_ptr(p, row);

        // prefetch the entire NEXT row into L2 (clamped to stay in bounds)
        {
            int nrow = row + gridDim.x;
            if (nrow >= NROWS) nrow = NROWS - 1;
            const int4* np = row_ptr(p, nrow);
            #pragma unroll
            for (int q = 0; q < 8; q++)
                pf_l2(np + tid + q * TPB);
        }

        u64 accA = 0, accB = 0;

        // batch 1: quads 0..3
        {
            int4 v0 = cp[tid];
            int4 v1 = cp[tid + 1 * TPB];
            int4 v2 = cp[tid + 2 * TPB];
            int4 v3 = cp[tid + 3 * TPB];
            float4 w0 = sth4[tid];
            float4 w1 = sth4[tid + 1 * TPB];
            float4 w2 = sth4[tid + 2 * TPB];
            float4 w3 = sth4[tid + 3 * TPB];
            proc_quad(v0, w0, accA, accB);
            proc_quad(v1, w1, accA, accB);
            proc_quad(v2, w2, accA, accB);
            proc_quad(v3, w3, accA, accB);
        }
        // batch 2: quads 4..6 + predicated tail quad (warp-uniform)
        {
            int4 v4 = cp[tid + 4 * TPB];
            int4 v5 = cp[tid + 5 * TPB];
            int4 v6 = cp[tid + 6 * TPB];
            int4 v7;
            if (hasTail) v7 = cp[tid + 7 * TPB];
            float4 w4 = sth4[tid + 4 * TPB];
            float4 w5 = sth4[tid + 5 * TPB];
            float4 w6 = sth4[tid + 6 * TPB];
            proc_quad(v4, w4, accA, accB);
            proc_quad(v5, w5, accA, accB);
            proc_quad(v6, w6, accA, accB);
            if (hasTail) {
                float4 w7 = sth4[tid + 7 * TPB];
                proc_quad(v7, w7, accA, accB);
            }
        }

        float a0, a1, b0, b1;
        unpack2(accA, a0, a1);
        unpack2(accB, b0, b1);
        float rowS = (a0 + b0) + (a1 + b1);
        if (lbl != 0) thrAcc += rowS;
    }

    accD += (double)thrAcc * (-0.1 / (double)usum);

    // ---- per-CTA reduction ----
    accD = warp_sum_d(accD);
    if ((tid & 31) == 0) redd[tid >> 5] = accD;
    __syncthreads();
    if (tid == 0) {
        double t = 0.0;
        #pragma unroll
        for (int w = 0; w < TPB / 32; w++) t += redd[w];
        g_part[blockIdx.x] = t;
        __threadfence();
        unsigned old = atomicAdd(&g_cnt, 1u);
        s_last = (old == gridDim.x - 1) ? 1 : 0;
    }
    __syncthreads();

    // ---- last CTA finalizes ----
    if (s_last) {
        double v = (tid < (int)gridDim.x) ? g_part[tid] : 0.0;
        v = warp_sum_d(v);
        if ((tid & 31) == 0) redd[tid >> 5] = v;
        __syncthreads();
        if (tid == 0) {
            double t = 0.0;
            #pragma unroll
            for (int w = 0; w < TPB / 32; w++) t += redd[w];
            out[0] = (float)(t / (double)NROWS);
            g_cnt = 0;                 // reset for next graph replay
        }
    }
}

extern "C" void kernel_launch(void* const* d_in, const int* in_sizes, int n_in,
                              void* d_out, int out_size) {
    const int*   dec = nullptr;
    const float* p   = nullptr;
    const float* th  = nullptr;
    for (int i = 0; i < n_in; ++i) {
        if (in_sizes[i] == 4 * SEQ)    dec = (const int*)d_in[i];
        else if (in_sizes[i] == VOCAB) th  = (const float*)d_in[i];
        else                           p   = (const float*)d_in[i];
    }

    cudaFuncSetAttribute(main_kernel,
                         cudaFuncAttributeMaxDynamicSharedMemorySize,
                         VOCAB * (int)sizeof(float));

    int sms = 0;
    cudaDeviceGetAttribute(&sms, cudaDevAttrMultiProcessorCount, 0);
    if (sms <= 0) sms = 148;
    if (sms > MAXCTA) sms = MAXCTA;

    main_kernel<<<sms, TPB, VOCAB * sizeof(float)>>>(p, dec, th, (float*)d_out);
}

// round 8
// speedup vs baseline: 1.2026x; 1.0693x over previous
#include <cuda_runtime.h>
#include <math.h>

#define VOCAB   32000
#define V4      8000                 // float4 per row
#define NROWS   4092                 // 4 * 1023
#define SEQ     1024
#define TPB     1024
#define TAILQ   (V4 - 7 * TPB)       // 832 tail quads (= 26 full warps)
#define MAXCTA  256

__device__ double   g_part[MAXCTA];
__device__ unsigned g_cnt = 0;

// raw MUFU.LG2 (full-range log2 approx, single instruction)
__device__ __forceinline__ float lg2(float x) {
    float r; asm("lg2.approx.f32 %0, %1;" : "=f"(r) : "f"(x)); return r;
}

// scalar fast log (prologue only): degree-5, |abs err| <= 2e-4
__device__ __forceinline__ float lnfast(float x) {
    int i = __float_as_int(x);
    int k = (i - 0x3F2AAAAB) & 0xFF800000;
    float f = __int_as_float(i - k) - 1.0f;
    float P = 0.2f;
    P = fmaf(P, f, -0.25f);
    P = fmaf(P, f,  0.33333334f);
    P = fmaf(P, f, -0.5f);
    P = fmaf(P, f,  1.0f);
    return fmaf(f, P, (float)k * 8.2629582e-8f);
}

__device__ __forceinline__ float warp_sum(float v) {
    #pragma unroll
    for (int o = 16; o; o >>= 1) v += __shfl_xor_sync(0xFFFFFFFFu, v, o);
    return v;
}
__device__ __forceinline__ double warp_sum_d(double v) {
    #pragma unroll
    for (int o = 16; o; o >>= 1) v += __shfl_xor_sync(0xFFFFFFFFu, v, o);
    return v;
}

// one quad: 4x (acc += w * lg2(v))
__device__ __forceinline__ void proc_quad(float4 v, float4 w,
                                          float& a0, float& a1,
                                          float& a2, float& a3) {
    a0 = fmaf(w.x, lg2(v.x), a0);
    a1 = fmaf(w.y, lg2(v.y), a1);
    a2 = fmaf(w.z, lg2(v.z), a2);
    a3 = fmaf(w.w, lg2(v.w), a3);
}

// row -> base quad pointer ( b*1024 + t = row + row/1023 )
__device__ __forceinline__ const float4* row_ptr(const float* p, int row) {
    int off = row + row / 1023;
    return reinterpret_cast<const float4*>(p + (size_t)off * VOCAB);
}

__global__ void __launch_bounds__(TPB, 1)
main_kernel(const float* __restrict__ p,
            const int*   __restrict__ dec,
            const float* __restrict__ th,
            float* __restrict__ out) {
    extern __shared__ float sth[];               // 32000 floats = 128 KB
    __shared__ float  redf[TPB / 32];
    __shared__ double redd[TPB / 32];
    __shared__ float  s_b[2];
    __shared__ int    s_last;

    const int tid = threadIdx.x;
    float4* sth4 = reinterpret_cast<float4*>(sth);
    const float4* th4 = reinterpret_cast<const float4*>(th);
    for (int i = tid; i < V4; i += TPB) sth4[i] = th4[i];
    __syncthreads();

    // ---- prologue: usum ----
    {
        float s = 0.f;
        for (int i = tid; i < VOCAB; i += TPB) s += sth[i];
        s = warp_sum(s);
        if ((tid & 31) == 0) redf[tid >> 5] = s;
        __syncthreads();
        if (tid == 0) {
            float t = 0.f;
            #pragma unroll
            for (int w = 0; w < TPB / 32; w++) t += redf[w];
            s_b[0] = t;
        }
        __syncthreads();
    }
    const float usum  = s_b[0];
    const float inv01 = 0.1f / usum;

    // ---- prologue: C1 = sum f(eps*u_v) ----
    {
        float c = 0.f;
        for (int i = tid; i < VOCAB; i += TPB) {
            float x = sth[i] * inv01;
            c += x * lnfast(x);
        }
        c = warp_sum(c);
        if ((tid & 31) == 0) redf[tid >> 5] = c;
        __syncthreads();
        if (tid == 0) {
            float t = 0.f;
            #pragma unroll
            for (int w = 0; w < TPB / 32; w++) t += redf[w];
            s_b[1] = t;
        }
        __syncthreads();
    }
    const float C1 = s_b[1];

    double accD = 0.0;

    // ---- label-dependent O(1)-per-row terms ----
    {
        const int gid = blockIdx.x * TPB + tid;
        if (gid < NROWS) {
            const int b = gid / 1023;
            const int t = gid - b * 1023;
            const int l = __ldg(&dec[b * SEQ + t + 1]);
            if (l != 0) {
                float pl = __ldg(p + (size_t)(b * SEQ + t) * VOCAB + l);
                float x  = sth[l] * inv01;
                accD += (double)(C1
                                 - x * logf(x)
                                 + (x + 0.9f) * logf(x + 0.9f)
                                 - 0.9f * logf(pl));
            }
        }
    }

    // ---- bulk: S_row(lg2) = sum_v th_v * lg2 p_v  via MUFU ----
    const bool hasTail = (tid < TAILQ);
    float thrAcc = 0.f;       // per-thread masked sum of w*lg2(p)

    for (int row = blockIdx.x; row < NROWS; row += gridDim.x) {
        const int b   = row / 1023;
        const int lbl = __ldg(&dec[b * SEQ + (row - b * 1023) + 1]);
        const float4* cp = row_ptr(p, row);

        float a0 = 0.f, a1 = 0.f, a2 = 0.f, a3 = 0.f;

        // batch 1: quads 0..3 (4 LDG.128 in flight)
        {
            float4 v0 = cp[tid];
            float4 v1 = cp[tid + 1 * TPB];
            float4 v2 = cp[tid + 2 * TPB];
            float4 v3 = cp[tid + 3 * TPB];
            proc_quad(v0, sth4[tid          ], a0, a1, a2, a3);
            proc_quad(v1, sth4[tid + 1 * TPB], a0, a1, a2, a3);
            proc_quad(v2, sth4[tid + 2 * TPB], a0, a1, a2, a3);
            proc_quad(v3, sth4[tid + 3 * TPB], a0, a1, a2, a3);
        }
        // batch 2: quads 4..6 + predicated tail quad (warp-uniform)
        {
            float4 v4 = cp[tid + 4 * TPB];
            float4 v5 = cp[tid + 5 * TPB];
            float4 v6 = cp[tid + 6 * TPB];
            float4 v7;
            if (hasTail) v7 = cp[tid + 7 * TPB];
            proc_quad(v4, sth4[tid + 4 * TPB], a0, a1, a2, a3);
            proc_quad(v5, sth4[tid + 5 * TPB], a0, a1, a2, a3);
            proc_quad(v6, sth4[tid + 6 * TPB], a0, a1, a2, a3);
            if (hasTail) proc_quad(v7, sth4[tid + 7 * TPB], a0, a1, a2, a3);
        }

        float rowS = (a0 + a1) + (a2 + a3);
        if (lbl != 0) thrAcc += rowS;
    }

    // fold: accD += -eps/usum * ln2 * thrAcc
    accD += (double)thrAcc * (-0.1 * 0.6931471805599453 / (double)usum);

    // ---- per-CTA reduction ----
    accD = warp_sum_d(accD);
    if ((tid & 31) == 0) redd[tid >> 5] = accD;
    __syncthreads();
    if (tid == 0) {
        double t = 0.0;
        #pragma unroll
        for (int w = 0; w < TPB / 32; w++) t += redd[w];
        g_part[blockIdx.x] = t;
        __threadfence();
        unsigned old = atomicAdd(&g_cnt, 1u);
        s_last = (old == gridDim.x - 1) ? 1 : 0;
    }
    __syncthreads();

    // ---- last CTA finalizes ----
    if (s_last) {
        double v = (tid < (int)gridDim.x) ? g_part[tid] : 0.0;
        v = warp_sum_d(v);
        if ((tid & 31) == 0) redd[tid >> 5] = v;
        __syncthreads();
        if (tid == 0) {
            double t = 0.0;
            #pragma unroll
            for (int w = 0; w < TPB / 32; w++) t += redd[w];
            out[0] = (float)(t / (double)NROWS);
            g_cnt = 0;                 // reset for next graph replay
        }
    }
}

extern "C" void kernel_launch(void* const* d_in, const int* in_sizes, int n_in,
                              void* d_out, int out_size) {
    const int*   dec = nullptr;
    const float* p   = nullptr;
    const float* th  = nullptr;
    for (int i = 0; i < n_in; ++i) {
        if (in_sizes[i] == 4 * SEQ)    dec = (const int*)d_in[i];
        else if (in_sizes[i] == VOCAB) th  = (const float*)d_in[i];
        else                           p   = (const float*)d_in[i];
    }

    cudaFuncSetAttribute(main_kernel,
                         cudaFuncAttributeMaxDynamicSharedMemorySize,
                         VOCAB * (int)sizeof(float));

    int sms = 0;
    cudaDeviceGetAttribute(&sms, cudaDevAttrMultiProcessorCount, 0);
    if (sms <= 0) sms = 148;
    if (sms > MAXCTA) sms = MAXCTA;

    main_kernel<<<sms, TPB, VOCAB * sizeof(float)>>>(p, dec, th, (float*)d_out);
}

// round 9
// speedup vs baseline: 1.2042x; 1.0014x over previous
#include <cuda_runtime.h>
#include <math.h>

#define VOCAB   32000
#define V4      8000                 // float4 per row
#define NROWS   4092                 // 4 * 1023
#define SEQ     1024
#define TPB     1024
#define TAILQ   (V4 - 7 * TPB)       // 832 tail quads (= 26 full warps)
#define MAXCTA  256

__device__ double   g_part[MAXCTA];
__device__ unsigned g_cnt = 0;

// raw MUFU.LG2 (full-range log2 approx, single instruction)
__device__ __forceinline__ float lg2(float x) {
    float r; asm("lg2.approx.f32 %0, %1;" : "=f"(r) : "f"(x)); return r;
}

// scalar fast log (prologue only): degree-5, |abs err| <= 2e-4
__device__ __forceinline__ float lnfast(float x) {
    int i = __float_as_int(x);
    int k = (i - 0x3F2AAAAB) & 0xFF800000;
    float f = __int_as_float(i - k) - 1.0f;
    float P = 0.2f;
    P = fmaf(P, f, -0.25f);
    P = fmaf(P, f,  0.33333334f);
    P = fmaf(P, f, -0.5f);
    P = fmaf(P, f,  1.0f);
    return fmaf(f, P, (float)k * 8.2629582e-8f);
}

__device__ __forceinline__ float warp_sum(float v) {
    #pragma unroll
    for (int o = 16; o; o >>= 1) v += __shfl_xor_sync(0xFFFFFFFFu, v, o);
    return v;
}
__device__ __forceinline__ double warp_sum_d(double v) {
    #pragma unroll
    for (int o = 16; o; o >>= 1) v += __shfl_xor_sync(0xFFFFFFFFu, v, o);
    return v;
}

// one quad: 2-accumulator form (lean on registers)
__device__ __forceinline__ void proc_quad(float4 v, float4 w, float& a0, float& a1) {
    a0 = fmaf(w.x, lg2(v.x), a0);
    a1 = fmaf(w.y, lg2(v.y), a1);
    a0 = fmaf(w.z, lg2(v.z), a0);
    a1 = fmaf(w.w, lg2(v.w), a1);
}

// row -> base quad pointer ( b*1024 + t = row + row/1023 )
__device__ __forceinline__ const float4* row_ptr(const float* p, int row) {
    int off = row + row / 1023;
    return reinterpret_cast<const float4*>(p + (size_t)off * VOCAB);
}

__global__ void __launch_bounds__(TPB, 1)
main_kernel(const float* __restrict__ p,
            const int*   __restrict__ dec,
            const float* __restrict__ th,
            float* __restrict__ out) {
    extern __shared__ float sth[];               // 32000 floats = 128 KB
    __shared__ float  redf[TPB / 32];
    __shared__ double redd[TPB / 32];
    __shared__ float  s_b[2];
    __shared__ int    s_last;

    const int tid = threadIdx.x;
    float4* sth4 = reinterpret_cast<float4*>(sth);
    const float4* th4 = reinterpret_cast<const float4*>(th);
    for (int i = tid; i < V4; i += TPB) sth4[i] = th4[i];
    __syncthreads();

    // ---- prologue: usum ----
    {
        float s = 0.f;
        for (int i = tid; i < VOCAB; i += TPB) s += sth[i];
        s = warp_sum(s);
        if ((tid & 31) == 0) redf[tid >> 5] = s;
        __syncthreads();
        if (tid == 0) {
            float t = 0.f;
            #pragma unroll
            for (int w = 0; w < TPB / 32; w++) t += redf[w];
            s_b[0] = t;
        }
        __syncthreads();
    }
    const float usum  = s_b[0];
    const float inv01 = 0.1f / usum;

    // ---- prologue: C1 = sum f(eps*u_v) ----
    {
        float c = 0.f;
        for (int i = tid; i < VOCAB; i += TPB) {
            float x = sth[i] * inv01;
            c += x * lnfast(x);
        }
        c = warp_sum(c);
        if ((tid & 31) == 0) redf[tid >> 5] = c;
        __syncthreads();
        if (tid == 0) {
            float t = 0.f;
            #pragma unroll
            for (int w = 0; w < TPB / 32; w++) t += redf[w];
            s_b[1] = t;
        }
        __syncthreads();
    }
    const float C1 = s_b[1];

    double accD = 0.0;

    // ---- label-dependent O(1)-per-row terms ----
    {
        const int gid = blockIdx.x * TPB + tid;
        if (gid < NROWS) {
            const int b = gid / 1023;
            const int t = gid - b * 1023;
            const int l = __ldg(&dec[b * SEQ + t + 1]);
            if (l != 0) {
                float pl = __ldg(p + (size_t)(b * SEQ + t) * VOCAB + l);
                float x  = sth[l] * inv01;
                accD += (double)(C1
                                 - x * logf(x)
                                 + (x + 0.9f) * logf(x + 0.9f)
                                 - 0.9f * logf(pl));
            }
        }
    }

    // ---- bulk: cross-row pipelined MUFU loop ----
    const bool hasTail = (tid < TAILQ);
    float thrAcc = 0.f;

    int row = blockIdx.x;
    if (row < NROWS) {
        const float4* cp = row_ptr(p, row);
        // preload all 8 quads of the first row
        float4 q0 = cp[tid];
        float4 q1 = cp[tid + 1 * TPB];
        float4 q2 = cp[tid + 2 * TPB];
        float4 q3 = cp[tid + 3 * TPB];
        float4 q4 = cp[tid + 4 * TPB];
        float4 q5 = cp[tid + 5 * TPB];
        float4 q6 = cp[tid + 6 * TPB];
        float4 q7;
        if (hasTail) q7 = cp[tid + 7 * TPB];

        while (true) {
            const int b   = row / 1023;
            const int lbl = __ldg(&dec[b * SEQ + (row - b * 1023) + 1]);

            float a0 = 0.f, a1 = 0.f;
            proc_quad(q0, sth4[tid          ], a0, a1);
            proc_quad(q1, sth4[tid + 1 * TPB], a0, a1);
            proc_quad(q2, sth4[tid + 2 * TPB], a0, a1);
            proc_quad(q3, sth4[tid + 3 * TPB], a0, a1);

            // refill head quads from the next row (re-read current on last iter)
            const int  nrow  = row + gridDim.x;
            const bool valid = (nrow < NROWS);
            const float4* np = valid ? row_ptr(p, nrow) : cp;
            q0 = np[tid];
            q1 = np[tid + 1 * TPB];
            q2 = np[tid + 2 * TPB];
            q3 = np[tid + 3 * TPB];

            proc_quad(q4, sth4[tid + 4 * TPB], a0, a1);
            proc_quad(q5, sth4[tid + 5 * TPB], a0, a1);
            proc_quad(q6, sth4[tid + 6 * TPB], a0, a1);
            if (hasTail) proc_quad(q7, sth4[tid + 7 * TPB], a0, a1);

            // refill tail quads from the next row
            q4 = np[tid + 4 * TPB];
            q5 = np[tid + 5 * TPB];
            q6 = np[tid + 6 * TPB];
            if (hasTail) q7 = np[tid + 7 * TPB];

            if (lbl != 0) thrAcc += a0 + a1;

            if (!valid) break;
            row = nrow;
            cp  = np;
        }
    }

    // fold: accD += -eps/usum * ln2 * thrAcc
    accD += (double)thrAcc * (-0.1 * 0.6931471805599453 / (double)usum);

    // ---- per-CTA reduction ----
    accD = warp_sum_d(accD);
    if ((tid & 31) == 0) redd[tid >> 5] = accD;
    __syncthreads();
    if (tid == 0) {
        double t = 0.0;
        #pragma unroll
        for (int w = 0; w < TPB / 32; w++) t += redd[w];
        g_part[blockIdx.x] = t;
        __threadfence();
        unsigned old = atomicAdd(&g_cnt, 1u);
        s_last = (old == gridDim.x - 1) ? 1 : 0;
    }
    __syncthreads();

    // ---- last CTA finalizes ----
    if (s_last) {
        double v = (tid < (int)gridDim.x) ? g_part[tid] : 0.0;
        v = warp_sum_d(v);
        if ((tid & 31) == 0) redd[tid >> 5] = v;
        __syncthreads();
        if (tid == 0) {
            double t = 0.0;
            #pragma unroll
            for (int w = 0; w < TPB / 32; w++) t += redd[w];
            out[0] = (float)(t / (double)NROWS);
            g_cnt = 0;                 // reset for next graph replay
        }
    }
}

extern "C" void kernel_launch(void* const* d_in, const int* in_sizes, int n_in,
                              void* d_out, int out_size) {
    const int*   dec = nullptr;
    const float* p   = nullptr;
    const float* th  = nullptr;
    for (int i = 0; i < n_in; ++i) {
        if (in_sizes[i] == 4 * SEQ)    dec = (const int*)d_in[i];
        else if (in_sizes[i] == VOCAB) th  = (const float*)d_in[i];
        else                           p   = (const float*)d_in[i];
    }

    cudaFuncSetAttribute(main_kernel,
                         cudaFuncAttributeMaxDynamicSharedMemorySize,
                         VOCAB * (int)sizeof(float));

    int sms = 0;
    cudaDeviceGetAttribute(&sms, cudaDevAttrMultiProcessorCount, 0);
    if (sms <= 0) sms = 148;
    if (sms > MAXCTA) sms = MAXCTA;

    main_kernel<<<sms, TPB, VOCAB * sizeof(float)>>>(p, dec, th, (float*)d_out);
}